// round 14
// baseline (speedup 1.0000x reference)
#include <cuda_runtime.h>
#include <math.h>

#define Bn 8
#define Ln 2048
#define Cn 7
#define Dn 512
#define Wn 24
#define NF 56
#define EPSf 1e-5f
#define TT 16
#define THRESH 1e-7f
#define DCUT 36.0f

// ---------------- scratch (device globals; allocation-free kernel_launch) ----
__device__ float g_xcomb[Bn*Ln*NF];
__device__ float g_wT[NF*3*Dn];
__device__ float g_c[(size_t)Bn*Ln*Dn];
__device__ float g_sq[Bn*Ln];
__device__ float g_sq64[Bn*Ln];
__device__ float g_sq128[Bn*Ln];
__device__ float g_sq256[Bn*Ln];
__device__ float g_pe[Ln*Dn];
__device__ float g_pef[Ln*Dn];
__device__ float g_pel[Ln*Dn];
__device__ float g_S[(size_t)Bn*Ln*Ln];
__device__ int   g_flag32[Bn*16*64];

// ---------------- helpers -----------------------------------------------------
__device__ __forceinline__ float totf(float x) {
    unsigned u;
    asm("cvt.rna.tf32.f32 %0, %1;" : "=r"(u) : "f"(x));
    return __uint_as_float(u);
}

__device__ __forceinline__ void mma_tf32(float* d, const unsigned* a, const unsigned* b) {
    asm volatile(
        "mma.sync.aligned.m16n8k8.row.col.f32.tf32.tf32.f32 "
        "{%0,%1,%2,%3}, {%4,%5,%6,%7}, {%8,%9}, {%0,%1,%2,%3};"
        : "+f"(d[0]), "+f"(d[1]), "+f"(d[2]), "+f"(d[3])
        : "r"(a[0]), "r"(a[1]), "r"(a[2]), "r"(a[3]), "r"(b[0]), "r"(b[1]));
}

__device__ __forceinline__ float blockReduce(float v, float* red) {
    #pragma unroll
    for (int o = 16; o; o >>= 1) v += __shfl_xor_sync(0xffffffffu, v, o);
    if ((threadIdx.x & 31) == 0) red[threadIdx.x >> 5] = v;
    __syncthreads();
    float s = red[0];
    #pragma unroll
    for (int i = 1; i < 8; i++) s += red[i];
    __syncthreads();
    return s;
}

// ---------------- 0) conv weight transpose ------------------------------------
__global__ __launch_bounds__(256)
void wtrans_kernel(const float* __restrict__ cw) {
    int idx = blockIdx.x * 256 + threadIdx.x;
    if (idx >= NF*3*Dn) return;
    int d = idx & (Dn-1);
    int f3k = idx >> 9;
    g_wT[idx] = cw[d*NF*3 + f3k];
}

// ---------------- 1) window stats + lags (smem-tiled) -------------------------
__global__ __launch_bounds__(256)
void features_kernel(const float* __restrict__ x) {
    __shared__ float sxf[152][Cn];
    int b  = blockIdx.y;
    int t0 = blockIdx.x * 128;
    int tid = threadIdx.x;
    const float* xb = x + (size_t)b*Ln*Cn;
    for (int i = tid; i < 151*Cn; i += 256) {
        int r = i / Cn, ch = i - r*Cn;
        int tt = t0 - 23 + r; tt = tt < 0 ? 0 : tt;
        sxf[r][ch] = xb[tt*Cn + ch];
    }
    __syncthreads();
    for (int i = tid; i < 128*Cn; i += 256) {
        int tl = i / Cn, ch = i - tl*Cn;
        float v[Wn];
        #pragma unroll
        for (int w = 0; w < Wn; w++) v[w] = sxf[tl + w][ch];
        float s = 0.f, mx = v[0], mn = v[0];
        #pragma unroll
        for (int w = 0; w < Wn; w++) { s += v[w]; mx = fmaxf(mx, v[w]); mn = fminf(mn, v[w]); }
        float mean = s * (1.0f/Wn);
        float m2 = 0.f;
        #pragma unroll
        for (int w = 0; w < Wn; w++) { float d = v[w]-mean; m2 += d*d; }
        float sd = sqrtf(m2 * (1.0f/(Wn-1)));
        float xc = v[Wn-1];
        int t = t0 + tl;
        float* o = g_xcomb + ((size_t)b*Ln + t)*NF;
        o[ch]      = xc;
        o[7  + ch] = mean;
        o[14 + ch] = mx;
        o[21 + ch] = mn;
        o[28 + ch] = sd;
        o[35 + ch] = xc - sxf[tl + 20][ch];
        o[42 + ch] = xc - sxf[tl + 18][ch];
        o[49 + ch] = xc - sxf[tl + 16][ch];
    }
}

// ---------------- 2) circular conv1d(k=3) + bias + LN + partial sumsq ---------
__global__ __launch_bounds__(256)
void conv_ln_kernel(const float* __restrict__ conv_b,
                    const float* __restrict__ gamma_c, const float* __restrict__ beta_c) {
    __shared__ float sx[TT+2][NF];
    __shared__ float semb[TT][Dn];
    int b  = blockIdx.y;
    int t0 = blockIdx.x * TT;
    int tid = threadIdx.x;
    for (int i = tid; i < (TT+2)*NF; i += 256) {
        int r = i / NF, f = i - r*NF;
        int tt = (t0 - 1 + r + Ln) & (Ln - 1);
        sx[r][f] = g_xcomb[((size_t)b*Ln + tt)*NF + f];
    }
    __syncthreads();
    int d0 = tid * 2;
    float acc0[TT], acc1[TT];
    float bb0 = conv_b[d0], bb1 = conv_b[d0+1];
    #pragma unroll
    for (int t = 0; t < TT; t++) { acc0[t] = bb0; acc1[t] = bb1; }
    const float2* wtp = (const float2*)g_wT;
    for (int f = 0; f < NF; f++) {
        float2 wk0 = wtp[(f*3+0)*(Dn/2) + tid];
        float2 wk1 = wtp[(f*3+1)*(Dn/2) + tid];
        float2 wk2 = wtp[(f*3+2)*(Dn/2) + tid];
        float sv[TT+2];
        #pragma unroll
        for (int r = 0; r < TT+2; r++) sv[r] = sx[r][f];
        #pragma unroll
        for (int t = 0; t < TT; t++) {
            acc0[t] += sv[t]*wk0.x + sv[t+1]*wk1.x + sv[t+2]*wk2.x;
            acc1[t] += sv[t]*wk0.y + sv[t+1]*wk1.y + sv[t+2]*wk2.y;
        }
    }
    #pragma unroll
    for (int t = 0; t < TT; t++) { semb[t][d0] = acc0[t]; semb[t][d0+1] = acc1[t]; }
    __syncthreads();
    int warp = tid >> 5, lane = tid & 31;
    for (int rr = warp; rr < TT; rr += 8) {
        float s = 0.f;
        for (int i = lane; i < Dn; i += 32) s += semb[rr][i];
        #pragma unroll
        for (int o = 16; o; o >>= 1) s += __shfl_xor_sync(0xffffffffu, s, o);
        float mu = s * (1.0f/Dn);
        float q = 0.f;
        for (int i = lane; i < Dn; i += 32) { float d = semb[rr][i]-mu; q += d*d; }
        #pragma unroll
        for (int o = 16; o; o >>= 1) q += __shfl_xor_sync(0xffffffffu, q, o);
        float inv = rsqrtf(q*(1.0f/Dn) + EPSf);
        int t = t0 + rr;
        float* cp = g_c + ((size_t)b*Ln + t)*Dn;
        float sq = 0.f, s64 = 0.f, s128 = 0.f, s256 = 0.f;
        for (int i = lane; i < Dn; i += 32) {
            float cv = (semb[rr][i]-mu)*inv*gamma_c[i] + beta_c[i];
            cp[i] = cv;
            float c2 = cv*cv;
            sq += c2;
            if (i < 64)  s64  += c2;
            if (i < 128) s128 += c2;
            if (i < 256) s256 += c2;
        }
        #pragma unroll
        for (int o = 16; o; o >>= 1) {
            sq   += __shfl_xor_sync(0xffffffffu, sq, o);
            s64  += __shfl_xor_sync(0xffffffffu, s64, o);
            s128 += __shfl_xor_sync(0xffffffffu, s128, o);
            s256 += __shfl_xor_sync(0xffffffffu, s256, o);
        }
        if (lane == 0) {
            g_sq[b*Ln + t]    = sq;
            g_sq64[b*Ln + t]  = s64;
            g_sq128[b*Ln + t] = s128;
            g_sq256[b*Ln + t] = s256;
        }
    }
}

// ---------------- 3) sinusoid PE + LN(pe) + LN(pe_learned) --------------------
__global__ __launch_bounds__(256)
void pe_kernel(const float* __restrict__ pe_learned,
               const float* __restrict__ gf, const float* __restrict__ bf,
               const float* __restrict__ gl, const float* __restrict__ bl) {
    __shared__ float red[8];
    int t = blockIdx.x;
    int tid = threadIdx.x;
    int dA = tid, dB = tid + 256;
    const float kdiv = -9.210340371976184f / (float)Dn;
    float divA = expf((float)(dA & ~1) * kdiv);
    float divB = expf((float)(dB & ~1) * kdiv);
    float sA, cA, sB, cB;
    sincosf((float)t * divA, &sA, &cA);
    sincosf((float)t * divB, &sB, &cB);
    float v0 = (dA & 1) ? cA : sA;
    float v1 = (dB & 1) ? cB : sB;
    g_pe[t*Dn + dA] = v0;
    g_pe[t*Dn + dB] = v1;
    float mu = blockReduce(v0 + v1, red) * (1.0f/Dn);
    float c0 = v0 - mu, c1 = v1 - mu;
    float var = blockReduce(c0*c0 + c1*c1, red) * (1.0f/Dn);
    float inv = rsqrtf(var + EPSf);
    g_pef[t*Dn + dA] = c0*inv*gf[dA] + bf[dA];
    g_pef[t*Dn + dB] = c1*inv*gf[dB] + bf[dB];
    float u0 = pe_learned[t*Dn + dA], u1 = pe_learned[t*Dn + dB];
    float mu2 = blockReduce(u0 + u1, red) * (1.0f/Dn);
    float e0 = u0 - mu2, e1 = u1 - mu2;
    float var2 = blockReduce(e0*e0 + e1*e1, red) * (1.0f/Dn);
    float inv2 = rsqrtf(var2 + EPSf);
    g_pel[t*Dn + dA] = e0*inv2*gl[dA] + bl[dA];
    g_pel[t*Dn + dB] = e1*inv2*gl[dB] + bl[dB];
}

// ---------------- 4) symmetric Gram (tf32 mma) + early checkpoint ladder ------
__global__ __launch_bounds__(256)
void gram_kernel() {
    __shared__ float As[2][128][20];
    __shared__ float Bs[2][128][20];
    __shared__ float redm[8];
    __shared__ float s_cgm[8];
    __shared__ float s_rgm[8][2];
    __shared__ int s_flag;
    int b = blockIdx.y;
    int rr_ = blockIdx.x, dia = 0;
    while (rr_ >= 16 - dia) { rr_ -= 16 - dia; dia++; }
    int ti = rr_, tj = rr_ + dia;
    const float* Cb = g_c + (size_t)b*Ln*Dn;
    int i0 = ti*128, j0 = tj*128;
    int tid = threadIdx.x;
    int warp = tid >> 5, lane = tid & 31;
    int wm = (warp >> 2) * 64;
    int wn = (warp & 3) * 32;
    int g = lane >> 2, th = lane & 3;

    int lrow = tid >> 1, lk = (tid & 1) * 8;
    const float* Ag = Cb + (size_t)(i0 + lrow)*Dn + lk;
    const float* Bg = Cb + (size_t)(j0 + lrow)*Dn + lk;

    float acc[4][4][4];
    #pragma unroll
    for (int i = 0; i < 4; i++)
        #pragma unroll
        for (int j = 0; j < 4; j++)
            #pragma unroll
            for (int q = 0; q < 4; q++) acc[i][j][q] = 0.f;

    float4 pa0 = *(const float4*)(Ag);
    float4 pa1 = *(const float4*)(Ag + 4);
    float4 pb0 = *(const float4*)(Bg);
    float4 pb1 = *(const float4*)(Bg + 4);
    #pragma unroll
    for (int q = 0; q < 4; q++) {
        As[0][lrow][lk+q]   = totf(((float*)&pa0)[q]);
        As[0][lrow][lk+4+q] = totf(((float*)&pa1)[q]);
        Bs[0][lrow][lk+q]   = totf(((float*)&pb0)[q]);
        Bs[0][lrow][lk+4+q] = totf(((float*)&pb1)[q]);
    }
    __syncthreads();
    int cur = 0;
    for (int kt = 0; kt < 32; kt++) {
        if (kt < 31) {
            int ko = (kt+1)*16;
            pa0 = *(const float4*)(Ag + ko);
            pa1 = *(const float4*)(Ag + ko + 4);
            pb0 = *(const float4*)(Bg + ko);
            pb1 = *(const float4*)(Bg + ko + 4);
        }
        #pragma unroll
        for (int k8 = 0; k8 < 16; k8 += 8) {
            unsigned af[4][4], bf_[4][2];
            #pragma unroll
            for (int fm = 0; fm < 4; fm++) {
                const float* ap = &As[cur][wm + fm*16 + g][k8 + th];
                af[fm][0] = __float_as_uint(ap[0]);
                af[fm][1] = __float_as_uint(ap[8*20]);
                af[fm][2] = __float_as_uint(ap[4]);
                af[fm][3] = __float_as_uint(ap[8*20 + 4]);
            }
            #pragma unroll
            for (int fn = 0; fn < 4; fn++) {
                const float* bp = &Bs[cur][wn + fn*8 + g][k8 + th];
                bf_[fn][0] = __float_as_uint(bp[0]);
                bf_[fn][1] = __float_as_uint(bp[4]);
            }
            #pragma unroll
            for (int fm = 0; fm < 4; fm++)
                #pragma unroll
                for (int fn = 0; fn < 4; fn++)
                    mma_tf32(acc[fm][fn], af[fm], bf_[fn]);
        }
        if (ti != tj && (kt == 3 || kt == 7 || kt == 15)) {
            const float* sqp = (kt == 3) ? g_sq64 : (kt == 7) ? g_sq128 : g_sq256;
            float sqj2[4][2];
            #pragma unroll
            for (int fn = 0; fn < 4; fn++) {
                int j = j0 + wn + fn*8 + th*2;
                sqj2[fn][0] = sqp[b*Ln + j];
                sqj2[fn][1] = sqp[b*Ln + j + 1];
            }
            float mind = 1e30f;
            #pragma unroll
            for (int fm = 0; fm < 4; fm++) {
                #pragma unroll
                for (int rr = 0; rr < 2; rr++) {
                    int i = i0 + wm + fm*16 + g + rr*8;
                    float sqi2 = sqp[b*Ln + i];
                    #pragma unroll
                    for (int fn = 0; fn < 4; fn++) {
                        float d0v = sqi2 + sqj2[fn][0] - 2.0f*acc[fm][fn][rr*2+0];
                        float d1v = sqi2 + sqj2[fn][1] - 2.0f*acc[fm][fn][rr*2+1];
                        mind = fminf(mind, fminf(d0v, d1v));
                    }
                }
            }
            #pragma unroll
            for (int o = 16; o; o >>= 1) mind = fminf(mind, __shfl_xor_sync(0xffffffffu, mind, o));
            if (lane == 0) redm[warp] = mind;
            __syncthreads();
            if (tid == 0) {
                float m = redm[0];
                #pragma unroll
                for (int i = 1; i < 8; i++) m = fminf(m, redm[i]);
                s_flag = (m > DCUT) ? 1 : 0;
            }
            __syncthreads();
            if (s_flag) {
                if (tid == 0) {
                    int* f0 = g_flag32 + (b*16 + ti)*64 + tj*4;
                    int* f1 = g_flag32 + (b*16 + tj)*64 + ti*4;
                    #pragma unroll
                    for (int q = 0; q < 4; q++) { f0[q] = 0; f1[q] = 0; }
                }
                return;
            }
        }
        if (kt < 31) {
            int nxt = cur ^ 1;
            #pragma unroll
            for (int q = 0; q < 4; q++) {
                As[nxt][lrow][lk+q]   = totf(((float*)&pa0)[q]);
                As[nxt][lrow][lk+4+q] = totf(((float*)&pa1)[q]);
                Bs[nxt][lrow][lk+q]   = totf(((float*)&pb0)[q]);
                Bs[nxt][lrow][lk+4+q] = totf(((float*)&pb1)[q]);
            }
            __syncthreads();
            cur = nxt;
        }
    }
    float sqj[4][2];
    #pragma unroll
    for (int fn = 0; fn < 4; fn++) {
        int j = j0 + wn + fn*8 + th*2;
        sqj[fn][0] = g_sq[b*Ln + j];
        sqj[fn][1] = g_sq[b*Ln + j + 1];
    }
    float cgmax = 0.f, rg0 = 0.f, rg1 = 0.f;
    #pragma unroll
    for (int fm = 0; fm < 4; fm++) {
        #pragma unroll
        for (int rr = 0; rr < 2; rr++) {
            int i = i0 + wm + fm*16 + g + rr*8;
            float sqi = g_sq[b*Ln + i];
            #pragma unroll
            for (int fn = 0; fn < 4; fn++) {
                float d0v = fmaxf(sqi + sqj[fn][0] - 2.0f*acc[fm][fn][rr*2+0], 0.0f);
                float d1v = fmaxf(sqi + sqj[fn][1] - 2.0f*acc[fm][fn][rr*2+1], 0.0f);
                float s0 = __expf(-0.5f * d0v);
                float s1 = __expf(-0.5f * d1v);
                acc[fm][fn][rr*2+0] = s0;
                acc[fm][fn][rr*2+1] = s1;
                float m01 = fmaxf(s0, s1);
                cgmax = fmaxf(cgmax, m01);
                if (fm < 2) rg0 = fmaxf(rg0, m01); else rg1 = fmaxf(rg1, m01);
            }
        }
    }
    #pragma unroll
    for (int o = 16; o; o >>= 1) {
        cgmax = fmaxf(cgmax, __shfl_xor_sync(0xffffffffu, cgmax, o));
        rg0   = fmaxf(rg0,   __shfl_xor_sync(0xffffffffu, rg0, o));
        rg1   = fmaxf(rg1,   __shfl_xor_sync(0xffffffffu, rg1, o));
    }
    if (lane == 0) { s_cgm[warp] = cgmax; s_rgm[warp][0] = rg0; s_rgm[warp][1] = rg1; }
    __syncthreads();
    if (tid == 0) {
        float tilem = s_cgm[0];
        #pragma unroll
        for (int i = 1; i < 8; i++) tilem = fmaxf(tilem, s_cgm[i]);
        int act = (tilem > THRESH) ? 1 : 0;
        s_flag = act;
        int* f0 = g_flag32 + (b*16 + ti)*64 + tj*4;
        int* f1 = g_flag32 + (b*16 + tj)*64 + ti*4;
        if (act) {
            #pragma unroll
            for (int cg = 0; cg < 4; cg++)
                f0[cg] = (fmaxf(s_cgm[cg], s_cgm[4+cg]) > THRESH) ? 1 : 0;
            if (ti != tj) {
                #pragma unroll
                for (int h = 0; h < 2; h++)
                    #pragma unroll
                    for (int fh = 0; fh < 2; fh++) {
                        float m = s_rgm[h*4+0][fh];
                        m = fmaxf(m, s_rgm[h*4+1][fh]);
                        m = fmaxf(m, s_rgm[h*4+2][fh]);
                        m = fmaxf(m, s_rgm[h*4+3][fh]);
                        f1[h*2+fh] = (m > THRESH) ? 1 : 0;
                    }
            }
        } else {
            #pragma unroll
            for (int q = 0; q < 4; q++) { f0[q] = 0; if (ti != tj) f1[q] = 0; }
        }
    }
    __syncthreads();
    if (s_flag) {
        float* Sb = g_S + (size_t)b*Ln*Ln;
        #pragma unroll
        for (int fm = 0; fm < 4; fm++) {
            #pragma unroll
            for (int rr = 0; rr < 2; rr++) {
                int i = i0 + wm + fm*16 + g + rr*8;
                #pragma unroll
                for (int fn = 0; fn < 4; fn++) {
                    int j = j0 + wn + fn*8 + th*2;
                    float s0 = acc[fm][fn][rr*2+0];
                    float s1 = acc[fm][fn][rr*2+1];
                    *(float2*)&Sb[(size_t)i*Ln + j] = make_float2(s0, s1);
                    if (ti != tj) {
                        Sb[(size_t)j*Ln + i]     = s0;
                        Sb[(size_t)(j+1)*Ln + i] = s1;
                    }
                }
            }
        }
    }
}

// ---------------- 5) sem (32x512, 1x8 warp grid) + fused rowsum + LN + mix ----
#define SEM_BS_F (2*16*520)
#define SEM_AS_F (2*32*20)
#define SEM_SMEM_BYTES ((SEM_BS_F + SEM_AS_F + 256 + 256 + 256) * 4)

__global__ __launch_bounds__(256)
void sem_kernel(const float* __restrict__ wp,
                const float* __restrict__ gt, const float* __restrict__ bt,
                float* __restrict__ out) {
    extern __shared__ float sm[];
    float* BsD = sm;
    float* AsD = sm + SEM_BS_F;
    float* srs = AsD + SEM_AS_F;
    float* rsum = srs + 256;
    float* rsq  = rsum + 256;
    __shared__ int s_list[64];
    __shared__ int s_nact;

    int b  = blockIdx.y;
    int i0 = blockIdx.x * 32;
    const float* Cb = g_c + (size_t)b*Ln*Dn;
    const float* Sb = g_S + (size_t)b*Ln*Ln;
    int tid = threadIdx.x;
    int warp = tid >> 5, lane = tid & 31;
    int wn = warp * 64;                      // warp col base (1x8 grid)
    int g = lane >> 2, th = lane & 3;

    if (tid == 0) {
        const int* fl = g_flag32 + (b*16 + (i0 >> 7))*64;
        int n = 0;
        for (int c = 0; c < 64; c++)
            if (fl[c]) s_list[n++] = c;
        s_nact = n;
    }
    __syncthreads();
    int total = s_nact * 2;

    int lrowA = tid >> 3, lkA = (tid & 7) * 2;
    int kB = tid >> 4, cB = tid & 15;
    const float* AgRow = Sb + (size_t)(i0 + lrowA)*Ln + lkA;
    const float* BgRow = Cb + (size_t)kB*Dn;

    float acc[2][8][4];
    #pragma unroll
    for (int mf = 0; mf < 2; mf++)
        #pragma unroll
        for (int fn = 0; fn < 8; fn++)
            #pragma unroll
            for (int q = 0; q < 4; q++) acc[mf][fn][q] = 0.f;

    float rs = 0.f;
    int k0 = s_list[0] * 32;
    float2 pa = *(const float2*)(AgRow + k0);
    float4 pb[8];
    #pragma unroll
    for (int q = 0; q < 8; q++)
        pb[q] = *(const float4*)(BgRow + (size_t)k0*Dn + (cB + q*16)*4);
    rs += pa.x + pa.y;
    {
        float* ad = AsD + lrowA*20 + lkA;
        ad[0] = totf(pa.x); ad[1] = totf(pa.y);
        #pragma unroll
        for (int q = 0; q < 8; q++) {
            float* bd = BsD + kB*520 + (cB + q*16)*4;
            bd[0] = totf(pb[q].x); bd[1] = totf(pb[q].y);
            bd[2] = totf(pb[q].z); bd[3] = totf(pb[q].w);
        }
    }
    __syncthreads();
    int cur = 0;
    for (int st = 0; st < total; st++) {
        if (st + 1 < total) {
            int kn = s_list[(st+1) >> 1] * 32 + ((st+1) & 1) * 16;
            pa = *(const float2*)(AgRow + kn);
            #pragma unroll
            for (int q = 0; q < 8; q++)
                pb[q] = *(const float4*)(BgRow + (size_t)kn*Dn + (cB + q*16)*4);
        }
        const float* AsC = AsD + cur*(32*20);
        const float* BsC = BsD + cur*(16*520);
        #pragma unroll
        for (int k8 = 0; k8 < 16; k8 += 8) {
            unsigned af[2][4];
            #pragma unroll
            for (int mf = 0; mf < 2; mf++) {
                const float* ap = AsC + (mf*16 + g)*20 + k8 + th;
                af[mf][0] = __float_as_uint(ap[0]);
                af[mf][1] = __float_as_uint(ap[8*20]);
                af[mf][2] = __float_as_uint(ap[4]);
                af[mf][3] = __float_as_uint(ap[8*20 + 4]);
            }
            #pragma unroll
            for (int fn = 0; fn < 8; fn++) {
                unsigned bf_[2];
                const float* bp = BsC + (k8 + th)*520 + wn + fn*8 + g;
                bf_[0] = __float_as_uint(bp[0]);
                bf_[1] = __float_as_uint(bp[4*520]);
                mma_tf32(acc[0][fn], af[0], bf_);
                mma_tf32(acc[1][fn], af[1], bf_);
            }
        }
        if (st + 1 < total) {
            int nxt = cur ^ 1;
            rs += pa.x + pa.y;
            float* ad = AsD + nxt*(32*20) + lrowA*20 + lkA;
            ad[0] = totf(pa.x); ad[1] = totf(pa.y);
            #pragma unroll
            for (int q = 0; q < 8; q++) {
                float* bd = BsD + nxt*(16*520) + kB*520 + (cB + q*16)*4;
                bd[0] = totf(pb[q].x); bd[1] = totf(pb[q].y);
                bd[2] = totf(pb[q].z); bd[3] = totf(pb[q].w);
            }
            __syncthreads();
            cur = nxt;
        }
    }
    __syncthreads();
    srs[tid] = rs;
    __syncthreads();

    // 4 rows per thread: row(mf,rr) = mf*16 + g + rr*8
    float rinvv[2][2];
    #pragma unroll
    for (int mf = 0; mf < 2; mf++)
        #pragma unroll
        for (int rr = 0; rr < 2; rr++) {
            int r = mf*16 + g + rr*8;
            float s = 0.f;
            #pragma unroll
            for (int k = 0; k < 8; k++) s += srs[r*8 + k];
            rinvv[mf][rr] = 1.0f / s;
        }

    // pass 1: v = c + pe + sem*rinv ; per-row partial sum/sumsq
    float psum[2][2] = {{0.f,0.f},{0.f,0.f}};
    float psq[2][2]  = {{0.f,0.f},{0.f,0.f}};
    #pragma unroll
    for (int mf = 0; mf < 2; mf++)
        #pragma unroll
        for (int fn = 0; fn < 8; fn++) {
            int j = wn + fn*8 + th*2;
            #pragma unroll
            for (int rr = 0; rr < 2; rr++) {
                int gi = i0 + mf*16 + g + rr*8;
                float2 cv = *(const float2*)&Cb[(size_t)gi*Dn + j];
                float2 pv = *(const float2*)&g_pe[gi*Dn + j];
                float v0 = cv.x + pv.x + acc[mf][fn][rr*2+0]*rinvv[mf][rr];
                float v1 = cv.y + pv.y + acc[mf][fn][rr*2+1]*rinvv[mf][rr];
                acc[mf][fn][rr*2+0] = v0;
                acc[mf][fn][rr*2+1] = v1;
                psum[mf][rr] += v0 + v1;
                psq[mf][rr]  += v0*v0 + v1*v1;
            }
        }
    #pragma unroll
    for (int o = 1; o <= 2; o <<= 1) {
        #pragma unroll
        for (int mf = 0; mf < 2; mf++)
            #pragma unroll
            for (int rr = 0; rr < 2; rr++) {
                psum[mf][rr] += __shfl_xor_sync(0xffffffffu, psum[mf][rr], o);
                psq[mf][rr]  += __shfl_xor_sync(0xffffffffu, psq[mf][rr], o);
            }
    }
    if (th == 0) {
        #pragma unroll
        for (int mf = 0; mf < 2; mf++)
            #pragma unroll
            for (int rr = 0; rr < 2; rr++) {
                int r = mf*16 + g + rr*8;
                rsum[r*8 + warp] = psum[mf][rr];
                rsq[r*8 + warp]  = psq[mf][rr];
            }
    }
    __syncthreads();
    float muv[2][2], invv[2][2];
    #pragma unroll
    for (int mf = 0; mf < 2; mf++)
        #pragma unroll
        for (int rr = 0; rr < 2; rr++) {
            int r = mf*16 + g + rr*8;
            float ts = 0.f, tq = 0.f;
            #pragma unroll
            for (int w = 0; w < 8; w++) { ts += rsum[r*8 + w]; tq += rsq[r*8 + w]; }
            float mu = ts * (1.0f/Dn);
            float var = tq * (1.0f/Dn) - mu*mu;
            muv[mf][rr] = mu;
            invv[mf][rr] = rsqrtf(var + EPSf);
        }

    float w0 = wp[0], w1 = wp[1], w2 = wp[2], w3 = wp[3];
    float mx = fmaxf(fmaxf(w0, w1), fmaxf(w2, w3));
    float e0 = expf(w0-mx), e1 = expf(w1-mx), e2 = expf(w2-mx), e3 = expf(w3-mx);
    float esum = 1.0f / (e0+e1+e2+e3);
    w0 = e0*esum; w1 = e1*esum; w2 = e2*esum; w3 = e3*esum;

    float* ob = out + ((size_t)b*Ln)*Dn;
    #pragma unroll
    for (int mf = 0; mf < 2; mf++)
        #pragma unroll
        for (int fn = 0; fn < 8; fn++) {
            int j = wn + fn*8 + th*2;
            float2 gv = *(const float2*)&gt[j];
            float2 bv = *(const float2*)&bt[j];
            #pragma unroll
            for (int rr = 0; rr < 2; rr++) {
                int gi = i0 + mf*16 + g + rr*8;
                float2 cv = *(const float2*)&Cb[(size_t)gi*Dn + j];
                float2 pf = *(const float2*)&g_pef[gi*Dn + j];
                float2 pl = *(const float2*)&g_pel[gi*Dn + j];
                float mu = muv[mf][rr], inv = invv[mf][rr];
                float t0v = (acc[mf][fn][rr*2+0]-mu)*inv*gv.x + bv.x;
                float t1v = (acc[mf][fn][rr*2+1]-mu)*inv*gv.y + bv.y;
                float2 ov;
                ov.x = w0*cv.x + w1*pf.x + w2*pl.x + w3*t0v;
                ov.y = w0*cv.y + w1*pf.y + w2*pl.y + w3*t1v;
                *(float2*)&ob[(size_t)gi*Dn + j] = ov;
            }
        }
}

// ---------------- launch ------------------------------------------------------
extern "C" void kernel_launch(void* const* d_in, const int* in_sizes, int n_in,
                              void* d_out, int out_size) {
    const float* x          = (const float*)d_in[0];
    const float* conv_w     = (const float*)d_in[1];
    const float* conv_b     = (const float*)d_in[2];
    const float* pe_learned = (const float*)d_in[3];
    const float* wp         = (const float*)d_in[4];
    const float* gamma_c    = (const float*)d_in[5];
    const float* beta_c     = (const float*)d_in[6];
    const float* gamma_f    = (const float*)d_in[7];
    const float* beta_f     = (const float*)d_in[8];
    const float* gamma_l    = (const float*)d_in[9];
    const float* beta_l     = (const float*)d_in[10];
    const float* gamma_t    = (const float*)d_in[11];
    const float* beta_t     = (const float*)d_in[12];

    cudaFuncSetAttribute(sem_kernel, cudaFuncAttributeMaxDynamicSharedMemorySize, SEM_SMEM_BYTES);

    wtrans_kernel<<<(NF*3*Dn + 255)/256, 256>>>(conv_w);
    features_kernel<<<dim3(Ln/128, Bn), 256>>>(x);
    conv_ln_kernel<<<dim3(Ln/TT, Bn), 256>>>(conv_b, gamma_c, beta_c);
    pe_kernel<<<Ln, 256>>>(pe_learned, gamma_f, beta_f, gamma_l, beta_l);
    gram_kernel<<<dim3(136, Bn), 256>>>();
    sem_kernel<<<dim3(Ln/32, Bn), 256, SEM_SMEM_BYTES>>>(wp, gamma_t, beta_t, (float*)d_out);
}

// round 15
// speedup vs baseline: 1.0707x; 1.0707x over previous
#include <cuda_runtime.h>
#include <math.h>

#define Bn 8
#define Ln 2048
#define Cn 7
#define Dn 512
#define Wn 24
#define NF 56
#define EPSf 1e-5f
#define TT 16
#define THRESH 1e-7f
#define DCUT 36.0f

// ---------------- scratch (device globals; allocation-free kernel_launch) ----
__device__ float g_xcomb[Bn*Ln*NF];
__device__ float g_wT[NF*3*Dn];
__device__ float g_c[(size_t)Bn*Ln*Dn];
__device__ float g_sq[Bn*Ln];
__device__ float g_sq64[Bn*Ln];
__device__ float g_sq128[Bn*Ln];
__device__ float g_sq256[Bn*Ln];
__device__ float g_pe[Ln*Dn];
__device__ float g_pef[Ln*Dn];
__device__ float g_pel[Ln*Dn];
__device__ float g_S[(size_t)Bn*Ln*Ln];
__device__ int   g_flag32[Bn*16*64];

// ---------------- helpers -----------------------------------------------------
__device__ __forceinline__ float totf(float x) {
    unsigned u;
    asm("cvt.rna.tf32.f32 %0, %1;" : "=r"(u) : "f"(x));
    return __uint_as_float(u);
}

__device__ __forceinline__ void mma_tf32(float* d, const unsigned* a, const unsigned* b) {
    asm volatile(
        "mma.sync.aligned.m16n8k8.row.col.f32.tf32.tf32.f32 "
        "{%0,%1,%2,%3}, {%4,%5,%6,%7}, {%8,%9}, {%0,%1,%2,%3};"
        : "+f"(d[0]), "+f"(d[1]), "+f"(d[2]), "+f"(d[3])
        : "r"(a[0]), "r"(a[1]), "r"(a[2]), "r"(a[3]), "r"(b[0]), "r"(b[1]));
}

__device__ __forceinline__ float blockReduce(float v, float* red) {
    #pragma unroll
    for (int o = 16; o; o >>= 1) v += __shfl_xor_sync(0xffffffffu, v, o);
    if ((threadIdx.x & 31) == 0) red[threadIdx.x >> 5] = v;
    __syncthreads();
    float s = red[0];
    #pragma unroll
    for (int i = 1; i < 8; i++) s += red[i];
    __syncthreads();
    return s;
}

// ---------------- 1) window stats + lags (smem-tiled) + weight transpose ------
__global__ __launch_bounds__(256)
void features_kernel(const float* __restrict__ x, const float* __restrict__ cw) {
    __shared__ float sxf[152][Cn];
    int b  = blockIdx.y;
    int t0 = blockIdx.x * 128;
    int tid = threadIdx.x;
    // fused conv-weight transpose (independent of the feature work below)
    int gtid = (blockIdx.y * gridDim.x + blockIdx.x) * 256 + tid;
    int gstride = gridDim.x * gridDim.y * 256;
    for (int idx = gtid; idx < NF*3*Dn; idx += gstride) {
        int d = idx & (Dn-1);
        int f3k = idx >> 9;
        g_wT[idx] = cw[d*NF*3 + f3k];
    }
    const float* xb = x + (size_t)b*Ln*Cn;
    for (int i = tid; i < 151*Cn; i += 256) {
        int r = i / Cn, ch = i - r*Cn;
        int tt = t0 - 23 + r; tt = tt < 0 ? 0 : tt;
        sxf[r][ch] = xb[tt*Cn + ch];
    }
    __syncthreads();
    for (int i = tid; i < 128*Cn; i += 256) {
        int tl = i / Cn, ch = i - tl*Cn;
        float v[Wn];
        #pragma unroll
        for (int w = 0; w < Wn; w++) v[w] = sxf[tl + w][ch];
        float s = 0.f, mx = v[0], mn = v[0];
        #pragma unroll
        for (int w = 0; w < Wn; w++) { s += v[w]; mx = fmaxf(mx, v[w]); mn = fminf(mn, v[w]); }
        float mean = s * (1.0f/Wn);
        float m2 = 0.f;
        #pragma unroll
        for (int w = 0; w < Wn; w++) { float d = v[w]-mean; m2 += d*d; }
        float sd = sqrtf(m2 * (1.0f/(Wn-1)));
        float xc = v[Wn-1];
        int t = t0 + tl;
        float* o = g_xcomb + ((size_t)b*Ln + t)*NF;
        o[ch]      = xc;
        o[7  + ch] = mean;
        o[14 + ch] = mx;
        o[21 + ch] = mn;
        o[28 + ch] = sd;
        o[35 + ch] = xc - sxf[tl + 20][ch];
        o[42 + ch] = xc - sxf[tl + 18][ch];
        o[49 + ch] = xc - sxf[tl + 16][ch];
    }
}

// ---------------- 2) circular conv1d(k=3) + bias + LN + partial sumsq ---------
__global__ __launch_bounds__(256)
void conv_ln_kernel(const float* __restrict__ conv_b,
                    const float* __restrict__ gamma_c, const float* __restrict__ beta_c) {
    __shared__ float sx[TT+2][NF];
    __shared__ float semb[TT][Dn];
    int b  = blockIdx.y;
    int t0 = blockIdx.x * TT;
    int tid = threadIdx.x;
    for (int i = tid; i < (TT+2)*NF; i += 256) {
        int r = i / NF, f = i - r*NF;
        int tt = (t0 - 1 + r + Ln) & (Ln - 1);
        sx[r][f] = g_xcomb[((size_t)b*Ln + tt)*NF + f];
    }
    __syncthreads();
    int d0 = tid * 2;
    float acc0[TT], acc1[TT];
    float bb0 = conv_b[d0], bb1 = conv_b[d0+1];
    #pragma unroll
    for (int t = 0; t < TT; t++) { acc0[t] = bb0; acc1[t] = bb1; }
    const float2* wtp = (const float2*)g_wT;
    for (int f = 0; f < NF; f++) {
        float2 wk0 = wtp[(f*3+0)*(Dn/2) + tid];
        float2 wk1 = wtp[(f*3+1)*(Dn/2) + tid];
        float2 wk2 = wtp[(f*3+2)*(Dn/2) + tid];
        float sv[TT+2];
        #pragma unroll
        for (int r = 0; r < TT+2; r++) sv[r] = sx[r][f];
        #pragma unroll
        for (int t = 0; t < TT; t++) {
            acc0[t] += sv[t]*wk0.x + sv[t+1]*wk1.x + sv[t+2]*wk2.x;
            acc1[t] += sv[t]*wk0.y + sv[t+1]*wk1.y + sv[t+2]*wk2.y;
        }
    }
    #pragma unroll
    for (int t = 0; t < TT; t++) { semb[t][d0] = acc0[t]; semb[t][d0+1] = acc1[t]; }
    __syncthreads();
    int warp = tid >> 5, lane = tid & 31;
    for (int rr = warp; rr < TT; rr += 8) {
        float s = 0.f;
        for (int i = lane; i < Dn; i += 32) s += semb[rr][i];
        #pragma unroll
        for (int o = 16; o; o >>= 1) s += __shfl_xor_sync(0xffffffffu, s, o);
        float mu = s * (1.0f/Dn);
        float q = 0.f;
        for (int i = lane; i < Dn; i += 32) { float d = semb[rr][i]-mu; q += d*d; }
        #pragma unroll
        for (int o = 16; o; o >>= 1) q += __shfl_xor_sync(0xffffffffu, q, o);
        float inv = rsqrtf(q*(1.0f/Dn) + EPSf);
        int t = t0 + rr;
        float* cp = g_c + ((size_t)b*Ln + t)*Dn;
        float sq = 0.f, s64 = 0.f, s128 = 0.f, s256 = 0.f;
        for (int i = lane; i < Dn; i += 32) {
            float cv = (semb[rr][i]-mu)*inv*gamma_c[i] + beta_c[i];
            cp[i] = cv;
            float c2 = cv*cv;
            sq += c2;
            if (i < 64)  s64  += c2;
            if (i < 128) s128 += c2;
            if (i < 256) s256 += c2;
        }
        #pragma unroll
        for (int o = 16; o; o >>= 1) {
            sq   += __shfl_xor_sync(0xffffffffu, sq, o);
            s64  += __shfl_xor_sync(0xffffffffu, s64, o);
            s128 += __shfl_xor_sync(0xffffffffu, s128, o);
            s256 += __shfl_xor_sync(0xffffffffu, s256, o);
        }
        if (lane == 0) {
            g_sq[b*Ln + t]    = sq;
            g_sq64[b*Ln + t]  = s64;
            g_sq128[b*Ln + t] = s128;
            g_sq256[b*Ln + t] = s256;
        }
    }
}

// ---------------- 3) sinusoid PE + LN(pe) + LN(pe_learned) --------------------
__global__ __launch_bounds__(256)
void pe_kernel(const float* __restrict__ pe_learned,
               const float* __restrict__ gf, const float* __restrict__ bf,
               const float* __restrict__ gl, const float* __restrict__ bl) {
    __shared__ float red[8];
    int t = blockIdx.x;
    int tid = threadIdx.x;
    int dA = tid, dB = tid + 256;
    const float kdiv = -9.210340371976184f / (float)Dn;
    float divA = expf((float)(dA & ~1) * kdiv);
    float divB = expf((float)(dB & ~1) * kdiv);
    float sA, cA, sB, cB;
    sincosf((float)t * divA, &sA, &cA);
    sincosf((float)t * divB, &sB, &cB);
    float v0 = (dA & 1) ? cA : sA;
    float v1 = (dB & 1) ? cB : sB;
    g_pe[t*Dn + dA] = v0;
    g_pe[t*Dn + dB] = v1;
    float mu = blockReduce(v0 + v1, red) * (1.0f/Dn);
    float c0 = v0 - mu, c1 = v1 - mu;
    float var = blockReduce(c0*c0 + c1*c1, red) * (1.0f/Dn);
    float inv = rsqrtf(var + EPSf);
    g_pef[t*Dn + dA] = c0*inv*gf[dA] + bf[dA];
    g_pef[t*Dn + dB] = c1*inv*gf[dB] + bf[dB];
    float u0 = pe_learned[t*Dn + dA], u1 = pe_learned[t*Dn + dB];
    float mu2 = blockReduce(u0 + u1, red) * (1.0f/Dn);
    float e0 = u0 - mu2, e1 = u1 - mu2;
    float var2 = blockReduce(e0*e0 + e1*e1, red) * (1.0f/Dn);
    float inv2 = rsqrtf(var2 + EPSf);
    g_pel[t*Dn + dA] = e0*inv2*gl[dA] + bl[dA];
    g_pel[t*Dn + dB] = e1*inv2*gl[dB] + bl[dB];
}

// ---------------- 4) symmetric Gram (tf32 mma) + early checkpoint ladder ------
__global__ __launch_bounds__(256)
void gram_kernel() {
    __shared__ float As[2][128][20];
    __shared__ float Bs[2][128][20];
    __shared__ float redm[8];
    __shared__ float s_cgm[8];
    __shared__ float s_rgm[8][2];
    __shared__ int s_flag;
    int b = blockIdx.y;
    int rr_ = blockIdx.x, dia = 0;
    while (rr_ >= 16 - dia) { rr_ -= 16 - dia; dia++; }
    int ti = rr_, tj = rr_ + dia;
    const float* Cb = g_c + (size_t)b*Ln*Dn;
    int i0 = ti*128, j0 = tj*128;
    int tid = threadIdx.x;
    int warp = tid >> 5, lane = tid & 31;
    int wm = (warp >> 2) * 64;
    int wn = (warp & 3) * 32;
    int g = lane >> 2, th = lane & 3;

    int lrow = tid >> 1, lk = (tid & 1) * 8;
    const float* Ag = Cb + (size_t)(i0 + lrow)*Dn + lk;
    const float* Bg = Cb + (size_t)(j0 + lrow)*Dn + lk;

    float acc[4][4][4];
    #pragma unroll
    for (int i = 0; i < 4; i++)
        #pragma unroll
        for (int j = 0; j < 4; j++)
            #pragma unroll
            for (int q = 0; q < 4; q++) acc[i][j][q] = 0.f;

    float4 pa0 = *(const float4*)(Ag);
    float4 pa1 = *(const float4*)(Ag + 4);
    float4 pb0 = *(const float4*)(Bg);
    float4 pb1 = *(const float4*)(Bg + 4);
    #pragma unroll
    for (int q = 0; q < 4; q++) {
        As[0][lrow][lk+q]   = totf(((float*)&pa0)[q]);
        As[0][lrow][lk+4+q] = totf(((float*)&pa1)[q]);
        Bs[0][lrow][lk+q]   = totf(((float*)&pb0)[q]);
        Bs[0][lrow][lk+4+q] = totf(((float*)&pb1)[q]);
    }
    __syncthreads();
    int cur = 0;
    for (int kt = 0; kt < 32; kt++) {
        if (kt < 31) {
            int ko = (kt+1)*16;
            pa0 = *(const float4*)(Ag + ko);
            pa1 = *(const float4*)(Ag + ko + 4);
            pb0 = *(const float4*)(Bg + ko);
            pb1 = *(const float4*)(Bg + ko + 4);
        }
        #pragma unroll
        for (int k8 = 0; k8 < 16; k8 += 8) {
            unsigned af[4][4], bf_[4][2];
            #pragma unroll
            for (int fm = 0; fm < 4; fm++) {
                const float* ap = &As[cur][wm + fm*16 + g][k8 + th];
                af[fm][0] = __float_as_uint(ap[0]);
                af[fm][1] = __float_as_uint(ap[8*20]);
                af[fm][2] = __float_as_uint(ap[4]);
                af[fm][3] = __float_as_uint(ap[8*20 + 4]);
            }
            #pragma unroll
            for (int fn = 0; fn < 4; fn++) {
                const float* bp = &Bs[cur][wn + fn*8 + g][k8 + th];
                bf_[fn][0] = __float_as_uint(bp[0]);
                bf_[fn][1] = __float_as_uint(bp[4]);
            }
            #pragma unroll
            for (int fm = 0; fm < 4; fm++)
                #pragma unroll
                for (int fn = 0; fn < 4; fn++)
                    mma_tf32(acc[fm][fn], af[fm], bf_[fn]);
        }
        if (ti != tj && (kt == 3 || kt == 7 || kt == 15)) {
            const float* sqp = (kt == 3) ? g_sq64 : (kt == 7) ? g_sq128 : g_sq256;
            float sqj2[4][2];
            #pragma unroll
            for (int fn = 0; fn < 4; fn++) {
                int j = j0 + wn + fn*8 + th*2;
                sqj2[fn][0] = sqp[b*Ln + j];
                sqj2[fn][1] = sqp[b*Ln + j + 1];
            }
            float mind = 1e30f;
            #pragma unroll
            for (int fm = 0; fm < 4; fm++) {
                #pragma unroll
                for (int rr = 0; rr < 2; rr++) {
                    int i = i0 + wm + fm*16 + g + rr*8;
                    float sqi2 = sqp[b*Ln + i];
                    #pragma unroll
                    for (int fn = 0; fn < 4; fn++) {
                        float d0v = sqi2 + sqj2[fn][0] - 2.0f*acc[fm][fn][rr*2+0];
                        float d1v = sqi2 + sqj2[fn][1] - 2.0f*acc[fm][fn][rr*2+1];
                        mind = fminf(mind, fminf(d0v, d1v));
                    }
                }
            }
            #pragma unroll
            for (int o = 16; o; o >>= 1) mind = fminf(mind, __shfl_xor_sync(0xffffffffu, mind, o));
            if (lane == 0) redm[warp] = mind;
            __syncthreads();
            if (tid == 0) {
                float m = redm[0];
                #pragma unroll
                for (int i = 1; i < 8; i++) m = fminf(m, redm[i]);
                s_flag = (m > DCUT) ? 1 : 0;
            }
            __syncthreads();
            if (s_flag) {
                if (tid == 0) {
                    int* f0 = g_flag32 + (b*16 + ti)*64 + tj*4;
                    int* f1 = g_flag32 + (b*16 + tj)*64 + ti*4;
                    #pragma unroll
                    for (int q = 0; q < 4; q++) { f0[q] = 0; f1[q] = 0; }
                }
                return;
            }
        }
        if (kt < 31) {
            int nxt = cur ^ 1;
            #pragma unroll
            for (int q = 0; q < 4; q++) {
                As[nxt][lrow][lk+q]   = totf(((float*)&pa0)[q]);
                As[nxt][lrow][lk+4+q] = totf(((float*)&pa1)[q]);
                Bs[nxt][lrow][lk+q]   = totf(((float*)&pb0)[q]);
                Bs[nxt][lrow][lk+4+q] = totf(((float*)&pb1)[q]);
            }
            __syncthreads();
            cur = nxt;
        }
    }
    float sqj[4][2];
    #pragma unroll
    for (int fn = 0; fn < 4; fn++) {
        int j = j0 + wn + fn*8 + th*2;
        sqj[fn][0] = g_sq[b*Ln + j];
        sqj[fn][1] = g_sq[b*Ln + j + 1];
    }
    float cgmax = 0.f, rg0 = 0.f, rg1 = 0.f;
    #pragma unroll
    for (int fm = 0; fm < 4; fm++) {
        #pragma unroll
        for (int rr = 0; rr < 2; rr++) {
            int i = i0 + wm + fm*16 + g + rr*8;
            float sqi = g_sq[b*Ln + i];
            #pragma unroll
            for (int fn = 0; fn < 4; fn++) {
                float d0v = fmaxf(sqi + sqj[fn][0] - 2.0f*acc[fm][fn][rr*2+0], 0.0f);
                float d1v = fmaxf(sqi + sqj[fn][1] - 2.0f*acc[fm][fn][rr*2+1], 0.0f);
                float s0 = __expf(-0.5f * d0v);
                float s1 = __expf(-0.5f * d1v);
                acc[fm][fn][rr*2+0] = s0;
                acc[fm][fn][rr*2+1] = s1;
                float m01 = fmaxf(s0, s1);
                cgmax = fmaxf(cgmax, m01);
                if (fm < 2) rg0 = fmaxf(rg0, m01); else rg1 = fmaxf(rg1, m01);
            }
        }
    }
    #pragma unroll
    for (int o = 16; o; o >>= 1) {
        cgmax = fmaxf(cgmax, __shfl_xor_sync(0xffffffffu, cgmax, o));
        rg0   = fmaxf(rg0,   __shfl_xor_sync(0xffffffffu, rg0, o));
        rg1   = fmaxf(rg1,   __shfl_xor_sync(0xffffffffu, rg1, o));
    }
    if (lane == 0) { s_cgm[warp] = cgmax; s_rgm[warp][0] = rg0; s_rgm[warp][1] = rg1; }
    __syncthreads();
    if (tid == 0) {
        float tilem = s_cgm[0];
        #pragma unroll
        for (int i = 1; i < 8; i++) tilem = fmaxf(tilem, s_cgm[i]);
        int act = (tilem > THRESH) ? 1 : 0;
        s_flag = act;
        int* f0 = g_flag32 + (b*16 + ti)*64 + tj*4;
        int* f1 = g_flag32 + (b*16 + tj)*64 + ti*4;
        if (act) {
            #pragma unroll
            for (int cg = 0; cg < 4; cg++)
                f0[cg] = (fmaxf(s_cgm[cg], s_cgm[4+cg]) > THRESH) ? 1 : 0;
            if (ti != tj) {
                #pragma unroll
                for (int h = 0; h < 2; h++)
                    #pragma unroll
                    for (int fh = 0; fh < 2; fh++) {
                        float m = s_rgm[h*4+0][fh];
                        m = fmaxf(m, s_rgm[h*4+1][fh]);
                        m = fmaxf(m, s_rgm[h*4+2][fh]);
                        m = fmaxf(m, s_rgm[h*4+3][fh]);
                        f1[h*2+fh] = (m > THRESH) ? 1 : 0;
                    }
            }
        } else {
            #pragma unroll
            for (int q = 0; q < 4; q++) { f0[q] = 0; if (ti != tj) f1[q] = 0; }
        }
    }
    __syncthreads();
    if (s_flag) {
        float* Sb = g_S + (size_t)b*Ln*Ln;
        #pragma unroll
        for (int fm = 0; fm < 4; fm++) {
            #pragma unroll
            for (int rr = 0; rr < 2; rr++) {
                int i = i0 + wm + fm*16 + g + rr*8;
                #pragma unroll
                for (int fn = 0; fn < 4; fn++) {
                    int j = j0 + wn + fn*8 + th*2;
                    float s0 = acc[fm][fn][rr*2+0];
                    float s1 = acc[fm][fn][rr*2+1];
                    *(float2*)&Sb[(size_t)i*Ln + j] = make_float2(s0, s1);
                    if (ti != tj) {
                        Sb[(size_t)j*Ln + i]     = s0;
                        Sb[(size_t)(j+1)*Ln + i] = s1;
                    }
                }
            }
        }
    }
}

// ---------------- 5) sem (32x512 tiles, 2x4 warp grid) + fused LN + mix -------
#define SEM_BS_F (2*16*520)
#define SEM_AS_F (2*32*20)
#define SEM_SMEM_BYTES ((SEM_BS_F + SEM_AS_F + 256 + 128 + 128) * 4)

__global__ __launch_bounds__(256)
void sem_kernel(const float* __restrict__ wp,
                const float* __restrict__ gt, const float* __restrict__ bt,
                float* __restrict__ out) {
    extern __shared__ float sm[];
    float* BsD = sm;
    float* AsD = sm + SEM_BS_F;
    float* srs = AsD + SEM_AS_F;
    float* rsum = srs + 256;
    float* rsq  = rsum + 128;
    __shared__ int s_list[64];
    __shared__ int s_nact;

    int b  = blockIdx.y;
    int i0 = blockIdx.x * 32;
    const float* Cb = g_c + (size_t)b*Ln*Dn;
    const float* Sb = g_S + (size_t)b*Ln*Ln;
    int tid = threadIdx.x;
    int warp = tid >> 5, lane = tid & 31;
    int wmr = (warp >> 2) * 16;
    int wn  = (warp & 3) * 128;
    int g = lane >> 2, th = lane & 3;

    if (tid == 0) {
        const int* fl = g_flag32 + (b*16 + (i0 >> 7))*64;
        int n = 0;
        for (int c = 0; c < 64; c++)
            if (fl[c]) s_list[n++] = c;
        s_nact = n;
    }
    __syncthreads();
    int total = s_nact * 2;

    int lrowA = tid >> 3, lkA = (tid & 7) * 2;
    int kB = tid >> 4, cB = tid & 15;
    const float* AgRow = Sb + (size_t)(i0 + lrowA)*Ln + lkA;
    const float* BgRow = Cb + (size_t)kB*Dn;

    float acc[16][4];
    #pragma unroll
    for (int i = 0; i < 16; i++)
        #pragma unroll
        for (int q = 0; q < 4; q++) acc[i][q] = 0.f;

    float rs = 0.f;
    int k0 = s_list[0] * 32;
    float2 pa = *(const float2*)(AgRow + k0);
    float4 pb[8];
    #pragma unroll
    for (int q = 0; q < 8; q++)
        pb[q] = *(const float4*)(BgRow + (size_t)k0*Dn + (cB + q*16)*4);
    rs += pa.x + pa.y;
    {
        float* ad = AsD + lrowA*20 + lkA;
        ad[0] = totf(pa.x); ad[1] = totf(pa.y);
        #pragma unroll
        for (int q = 0; q < 8; q++) {
            float* bd = BsD + kB*520 + (cB + q*16)*4;
            bd[0] = totf(pb[q].x); bd[1] = totf(pb[q].y);
            bd[2] = totf(pb[q].z); bd[3] = totf(pb[q].w);
        }
    }
    __syncthreads();
    int cur = 0;
    for (int st = 0; st < total; st++) {
        if (st + 1 < total) {
            int kn = s_list[(st+1) >> 1] * 32 + ((st+1) & 1) * 16;
            pa = *(const float2*)(AgRow + kn);
            #pragma unroll
            for (int q = 0; q < 8; q++)
                pb[q] = *(const float4*)(BgRow + (size_t)kn*Dn + (cB + q*16)*4);
        }
        const float* AsC = AsD + cur*(32*20);
        const float* BsC = BsD + cur*(16*520);
        #pragma unroll
        for (int k8 = 0; k8 < 16; k8 += 8) {
            unsigned af[4];
            const float* ap = AsC + (wmr + g)*20 + k8 + th;
            af[0] = __float_as_uint(ap[0]);
            af[1] = __float_as_uint(ap[8*20]);
            af[2] = __float_as_uint(ap[4]);
            af[3] = __float_as_uint(ap[8*20 + 4]);
            #pragma unroll
            for (int fn = 0; fn < 16; fn++) {
                unsigned bf_[2];
                const float* bp = BsC + (k8 + th)*520 + wn + fn*8 + g;
                bf_[0] = __float_as_uint(bp[0]);
                bf_[1] = __float_as_uint(bp[4*520]);
                mma_tf32(acc[fn], af, bf_);
            }
        }
        if (st + 1 < total) {
            int nxt = cur ^ 1;
            rs += pa.x + pa.y;
            float* ad = AsD + nxt*(32*20) + lrowA*20 + lkA;
            ad[0] = totf(pa.x); ad[1] = totf(pa.y);
            #pragma unroll
            for (int q = 0; q < 8; q++) {
                float* bd = BsD + nxt*(16*520) + kB*520 + (cB + q*16)*4;
                bd[0] = totf(pb[q].x); bd[1] = totf(pb[q].y);
                bd[2] = totf(pb[q].z); bd[3] = totf(pb[q].w);
            }
            __syncthreads();
            cur = nxt;
        }
    }
    __syncthreads();
    srs[tid] = rs;
    __syncthreads();

    int r0 = wmr + g, r1 = wmr + g + 8;
    float rsum0 = 0.f, rsum1 = 0.f;
    #pragma unroll
    for (int k = 0; k < 8; k++) { rsum0 += srs[r0*8 + k]; rsum1 += srs[r1*8 + k]; }
    float rinv0 = 1.0f / rsum0, rinv1 = 1.0f / rsum1;

    float sum0 = 0.f, sq0 = 0.f, sum1 = 0.f, sq1 = 0.f;
    int gi0 = i0 + r0, gi1 = i0 + r1;
    #pragma unroll
    for (int fn = 0; fn < 16; fn++) {
        int j = wn + fn*8 + th*2;
        float2 cv0 = *(const float2*)&Cb[(size_t)gi0*Dn + j];
        float2 pv0 = *(const float2*)&g_pe[gi0*Dn + j];
        float v00 = cv0.x + pv0.x + acc[fn][0]*rinv0;
        float v01 = cv0.y + pv0.y + acc[fn][1]*rinv0;
        acc[fn][0] = v00; acc[fn][1] = v01;
        sum0 += v00 + v01; sq0 += v00*v00 + v01*v01;
        float2 cv1 = *(const float2*)&Cb[(size_t)gi1*Dn + j];
        float2 pv1 = *(const float2*)&g_pe[gi1*Dn + j];
        float v10 = cv1.x + pv1.x + acc[fn][2]*rinv1;
        float v11 = cv1.y + pv1.y + acc[fn][3]*rinv1;
        acc[fn][2] = v10; acc[fn][3] = v11;
        sum1 += v10 + v11; sq1 += v10*v10 + v11*v11;
    }
    #pragma unroll
    for (int o = 1; o <= 2; o <<= 1) {
        sum0 += __shfl_xor_sync(0xffffffffu, sum0, o);
        sq0  += __shfl_xor_sync(0xffffffffu, sq0, o);
        sum1 += __shfl_xor_sync(0xffffffffu, sum1, o);
        sq1  += __shfl_xor_sync(0xffffffffu, sq1, o);
    }
    if (th == 0) {
        rsum[r0*4 + (warp & 3)] = sum0;  rsq[r0*4 + (warp & 3)] = sq0;
        rsum[r1*4 + (warp & 3)] = sum1;  rsq[r1*4 + (warp & 3)] = sq1;
    }
    __syncthreads();
    float ts0 = rsum[r0*4] + rsum[r0*4+1] + rsum[r0*4+2] + rsum[r0*4+3];
    float tq0 = rsq[r0*4]  + rsq[r0*4+1]  + rsq[r0*4+2]  + rsq[r0*4+3];
    float ts1 = rsum[r1*4] + rsum[r1*4+1] + rsum[r1*4+2] + rsum[r1*4+3];
    float tq1 = rsq[r1*4]  + rsq[r1*4+1]  + rsq[r1*4+2]  + rsq[r1*4+3];
    float mu0 = ts0 * (1.0f/Dn);
    float var0 = tq0 * (1.0f/Dn) - mu0*mu0;
    float inv0 = rsqrtf(var0 + EPSf);
    float mu1 = ts1 * (1.0f/Dn);
    float var1 = tq1 * (1.0f/Dn) - mu1*mu1;
    float inv1 = rsqrtf(var1 + EPSf);

    float w0 = wp[0], w1 = wp[1], w2 = wp[2], w3 = wp[3];
    float mx = fmaxf(fmaxf(w0, w1), fmaxf(w2, w3));
    float e0 = expf(w0-mx), e1 = expf(w1-mx), e2 = expf(w2-mx), e3 = expf(w3-mx);
    float esum = 1.0f / (e0+e1+e2+e3);
    w0 = e0*esum; w1 = e1*esum; w2 = e2*esum; w3 = e3*esum;

    float* ob = out + ((size_t)b*Ln)*Dn;
    #pragma unroll
    for (int fn = 0; fn < 16; fn++) {
        int j = wn + fn*8 + th*2;
        float2 gv = *(const float2*)&gt[j];
        float2 bv = *(const float2*)&bt[j];
        {
            float2 cv = *(const float2*)&Cb[(size_t)gi0*Dn + j];
            float2 pf = *(const float2*)&g_pef[gi0*Dn + j];
            float2 pl = *(const float2*)&g_pel[gi0*Dn + j];
            float t0v = (acc[fn][0]-mu0)*inv0*gv.x + bv.x;
            float t1v = (acc[fn][1]-mu0)*inv0*gv.y + bv.y;
            float2 ov;
            ov.x = w0*cv.x + w1*pf.x + w2*pl.x + w3*t0v;
            ov.y = w0*cv.y + w1*pf.y + w2*pl.y + w3*t1v;
            *(float2*)&ob[(size_t)gi0*Dn + j] = ov;
        }
        {
            float2 cv = *(const float2*)&Cb[(size_t)gi1*Dn + j];
            float2 pf = *(const float2*)&g_pef[gi1*Dn + j];
            float2 pl = *(const float2*)&g_pel[gi1*Dn + j];
            float t0v = (acc[fn][2]-mu1)*inv1*gv.x + bv.x;
            float t1v = (acc[fn][3]-mu1)*inv1*gv.y + bv.y;
            float2 ov;
            ov.x = w0*cv.x + w1*pf.x + w2*pl.x + w3*t0v;
            ov.y = w0*cv.y + w1*pf.y + w2*pl.y + w3*t1v;
            *(float2*)&ob[(size_t)gi1*Dn + j] = ov;
        }
    }
}

// ---------------- launch ------------------------------------------------------
extern "C" void kernel_launch(void* const* d_in, const int* in_sizes, int n_in,
                              void* d_out, int out_size) {
    const float* x          = (const float*)d_in[0];
    const float* conv_w     = (const float*)d_in[1];
    const float* conv_b     = (const float*)d_in[2];
    const float* pe_learned = (const float*)d_in[3];
    const float* wp         = (const float*)d_in[4];
    const float* gamma_c    = (const float*)d_in[5];
    const float* beta_c     = (const float*)d_in[6];
    const float* gamma_f    = (const float*)d_in[7];
    const float* beta_f     = (const float*)d_in[8];
    const float* gamma_l    = (const float*)d_in[9];
    const float* beta_l     = (const float*)d_in[10];
    const float* gamma_t    = (const float*)d_in[11];
    const float* beta_t     = (const float*)d_in[12];

    cudaFuncSetAttribute(sem_kernel, cudaFuncAttributeMaxDynamicSharedMemorySize, SEM_SMEM_BYTES);

    features_kernel<<<dim3(Ln/128, Bn), 256>>>(x, conv_w);
    conv_ln_kernel<<<dim3(Ln/TT, Bn), 256>>>(conv_b, gamma_c, beta_c);
    pe_kernel<<<Ln, 256>>>(pe_learned, gamma_f, beta_f, gamma_l, beta_l);
    gram_kernel<<<dim3(136, Bn), 256>>>();
    sem_kernel<<<dim3(Ln/32, Bn), 256, SEM_SMEM_BYTES>>>(wp, gamma_t, beta_t, (float*)d_out);
}

// round 16
// speedup vs baseline: 1.1451x; 1.0695x over previous
#include <cuda_runtime.h>
#include <math.h>

#define Bn 8
#define Ln 2048
#define Cn 7
#define Dn 512
#define Wn 24
#define NF 56
#define EPSf 1e-5f
#define TT 16
#define THRESH 1e-7f
#define DCUT 36.0f

// ---------------- scratch (device globals; allocation-free kernel_launch) ----
__device__ float g_xcomb[Bn*Ln*NF];
__device__ float g_wT[NF*3*Dn];
__device__ float g_c[(size_t)Bn*Ln*Dn];
__device__ float g_sq[Bn*Ln];
__device__ float g_sq64[Bn*Ln];
__device__ float g_sq128[Bn*Ln];
__device__ float g_sq256[Bn*Ln];
__device__ float g_pe[Ln*Dn];
__device__ float g_pef[Ln*Dn];
__device__ float g_pel[Ln*Dn];
__device__ float g_S[(size_t)Bn*Ln*Ln];
__device__ int   g_flagB[Bn*64*64];      // per (32-row chunk) x (32-col chunk) activity

// ---------------- helpers -----------------------------------------------------
__device__ __forceinline__ float totf(float x) {
    unsigned u;
    asm("cvt.rna.tf32.f32 %0, %1;" : "=r"(u) : "f"(x));
    return __uint_as_float(u);
}

__device__ __forceinline__ void mma_tf32(float* d, const unsigned* a, const unsigned* b) {
    asm volatile(
        "mma.sync.aligned.m16n8k8.row.col.f32.tf32.tf32.f32 "
        "{%0,%1,%2,%3}, {%4,%5,%6,%7}, {%8,%9}, {%0,%1,%2,%3};"
        : "+f"(d[0]), "+f"(d[1]), "+f"(d[2]), "+f"(d[3])
        : "r"(a[0]), "r"(a[1]), "r"(a[2]), "r"(a[3]), "r"(b[0]), "r"(b[1]));
}

__device__ __forceinline__ float blockReduce(float v, float* red) {
    #pragma unroll
    for (int o = 16; o; o >>= 1) v += __shfl_xor_sync(0xffffffffu, v, o);
    if ((threadIdx.x & 31) == 0) red[threadIdx.x >> 5] = v;
    __syncthreads();
    float s = red[0];
    #pragma unroll
    for (int i = 1; i < 8; i++) s += red[i];
    __syncthreads();
    return s;
}

// ---------------- 1) window stats + lags (smem-tiled) + weight transpose ------
__global__ __launch_bounds__(256)
void features_kernel(const float* __restrict__ x, const float* __restrict__ cw) {
    __shared__ float sxf[152][Cn];
    int b  = blockIdx.y;
    int t0 = blockIdx.x * 128;
    int tid = threadIdx.x;
    int gtid = (blockIdx.y * gridDim.x + blockIdx.x) * 256 + tid;
    int gstride = gridDim.x * gridDim.y * 256;
    for (int idx = gtid; idx < NF*3*Dn; idx += gstride) {
        int d = idx & (Dn-1);
        int f3k = idx >> 9;
        g_wT[idx] = cw[d*NF*3 + f3k];
    }
    const float* xb = x + (size_t)b*Ln*Cn;
    for (int i = tid; i < 151*Cn; i += 256) {
        int r = i / Cn, ch = i - r*Cn;
        int tt = t0 - 23 + r; tt = tt < 0 ? 0 : tt;
        sxf[r][ch] = xb[tt*Cn + ch];
    }
    __syncthreads();
    for (int i = tid; i < 128*Cn; i += 256) {
        int tl = i / Cn, ch = i - tl*Cn;
        float v[Wn];
        #pragma unroll
        for (int w = 0; w < Wn; w++) v[w] = sxf[tl + w][ch];
        float s = 0.f, mx = v[0], mn = v[0];
        #pragma unroll
        for (int w = 0; w < Wn; w++) { s += v[w]; mx = fmaxf(mx, v[w]); mn = fminf(mn, v[w]); }
        float mean = s * (1.0f/Wn);
        float m2 = 0.f;
        #pragma unroll
        for (int w = 0; w < Wn; w++) { float d = v[w]-mean; m2 += d*d; }
        float sd = sqrtf(m2 * (1.0f/(Wn-1)));
        float xc = v[Wn-1];
        int t = t0 + tl;
        float* o = g_xcomb + ((size_t)b*Ln + t)*NF;
        o[ch]      = xc;
        o[7  + ch] = mean;
        o[14 + ch] = mx;
        o[21 + ch] = mn;
        o[28 + ch] = sd;
        o[35 + ch] = xc - sxf[tl + 20][ch];
        o[42 + ch] = xc - sxf[tl + 18][ch];
        o[49 + ch] = xc - sxf[tl + 16][ch];
    }
}

// ---------------- 2) circular conv1d(k=3) + bias + LN + partial sumsq ---------
__global__ __launch_bounds__(256)
void conv_ln_kernel(const float* __restrict__ conv_b,
                    const float* __restrict__ gamma_c, const float* __restrict__ beta_c) {
    __shared__ float sx[TT+2][NF];
    __shared__ float semb[TT][Dn];
    int b  = blockIdx.y;
    int t0 = blockIdx.x * TT;
    int tid = threadIdx.x;
    for (int i = tid; i < (TT+2)*NF; i += 256) {
        int r = i / NF, f = i - r*NF;
        int tt = (t0 - 1 + r + Ln) & (Ln - 1);
        sx[r][f] = g_xcomb[((size_t)b*Ln + tt)*NF + f];
    }
    __syncthreads();
    int d0 = tid * 2;
    float acc0[TT], acc1[TT];
    float bb0 = conv_b[d0], bb1 = conv_b[d0+1];
    #pragma unroll
    for (int t = 0; t < TT; t++) { acc0[t] = bb0; acc1[t] = bb1; }
    const float2* wtp = (const float2*)g_wT;
    for (int f = 0; f < NF; f++) {
        float2 wk0 = wtp[(f*3+0)*(Dn/2) + tid];
        float2 wk1 = wtp[(f*3+1)*(Dn/2) + tid];
        float2 wk2 = wtp[(f*3+2)*(Dn/2) + tid];
        float sv[TT+2];
        #pragma unroll
        for (int r = 0; r < TT+2; r++) sv[r] = sx[r][f];
        #pragma unroll
        for (int t = 0; t < TT; t++) {
            acc0[t] += sv[t]*wk0.x + sv[t+1]*wk1.x + sv[t+2]*wk2.x;
            acc1[t] += sv[t]*wk0.y + sv[t+1]*wk1.y + sv[t+2]*wk2.y;
        }
    }
    #pragma unroll
    for (int t = 0; t < TT; t++) { semb[t][d0] = acc0[t]; semb[t][d0+1] = acc1[t]; }
    __syncthreads();
    int warp = tid >> 5, lane = tid & 31;
    for (int rr = warp; rr < TT; rr += 8) {
        float s = 0.f;
        for (int i = lane; i < Dn; i += 32) s += semb[rr][i];
        #pragma unroll
        for (int o = 16; o; o >>= 1) s += __shfl_xor_sync(0xffffffffu, s, o);
        float mu = s * (1.0f/Dn);
        float q = 0.f;
        for (int i = lane; i < Dn; i += 32) { float d = semb[rr][i]-mu; q += d*d; }
        #pragma unroll
        for (int o = 16; o; o >>= 1) q += __shfl_xor_sync(0xffffffffu, q, o);
        float inv = rsqrtf(q*(1.0f/Dn) + EPSf);
        int t = t0 + rr;
        float* cp = g_c + ((size_t)b*Ln + t)*Dn;
        float sq = 0.f, s64 = 0.f, s128 = 0.f, s256 = 0.f;
        for (int i = lane; i < Dn; i += 32) {
            float cv = (semb[rr][i]-mu)*inv*gamma_c[i] + beta_c[i];
            cp[i] = cv;
            float c2 = cv*cv;
            sq += c2;
            if (i < 64)  s64  += c2;
            if (i < 128) s128 += c2;
            if (i < 256) s256 += c2;
        }
        #pragma unroll
        for (int o = 16; o; o >>= 1) {
            sq   += __shfl_xor_sync(0xffffffffu, sq, o);
            s64  += __shfl_xor_sync(0xffffffffu, s64, o);
            s128 += __shfl_xor_sync(0xffffffffu, s128, o);
            s256 += __shfl_xor_sync(0xffffffffu, s256, o);
        }
        if (lane == 0) {
            g_sq[b*Ln + t]    = sq;
            g_sq64[b*Ln + t]  = s64;
            g_sq128[b*Ln + t] = s128;
            g_sq256[b*Ln + t] = s256;
        }
    }
}

// ---------------- 3) sinusoid PE + LN(pe) + LN(pe_learned) --------------------
__global__ __launch_bounds__(256)
void pe_kernel(const float* __restrict__ pe_learned,
               const float* __restrict__ gf, const float* __restrict__ bf,
               const float* __restrict__ gl, const float* __restrict__ bl) {
    __shared__ float red[8];
    int t = blockIdx.x;
    int tid = threadIdx.x;
    int dA = tid, dB = tid + 256;
    const float kdiv = -9.210340371976184f / (float)Dn;
    float divA = expf((float)(dA & ~1) * kdiv);
    float divB = expf((float)(dB & ~1) * kdiv);
    float sA, cA, sB, cB;
    sincosf((float)t * divA, &sA, &cA);
    sincosf((float)t * divB, &sB, &cB);
    float v0 = (dA & 1) ? cA : sA;
    float v1 = (dB & 1) ? cB : sB;
    g_pe[t*Dn + dA] = v0;
    g_pe[t*Dn + dB] = v1;
    float mu = blockReduce(v0 + v1, red) * (1.0f/Dn);
    float c0 = v0 - mu, c1 = v1 - mu;
    float var = blockReduce(c0*c0 + c1*c1, red) * (1.0f/Dn);
    float inv = rsqrtf(var + EPSf);
    g_pef[t*Dn + dA] = c0*inv*gf[dA] + bf[dA];
    g_pef[t*Dn + dB] = c1*inv*gf[dB] + bf[dB];
    float u0 = pe_learned[t*Dn + dA], u1 = pe_learned[t*Dn + dB];
    float mu2 = blockReduce(u0 + u1, red) * (1.0f/Dn);
    float e0 = u0 - mu2, e1 = u1 - mu2;
    float var2 = blockReduce(e0*e0 + e1*e1, red) * (1.0f/Dn);
    float inv2 = rsqrtf(var2 + EPSf);
    g_pel[t*Dn + dA] = e0*inv2*gl[dA] + bl[dA];
    g_pel[t*Dn + dB] = e1*inv2*gl[dB] + bl[dB];
}

// ---------------- 4) symmetric Gram (tf32 mma) + ladder + 32x32 block flags ---
__global__ __launch_bounds__(256)
void gram_kernel() {
    __shared__ float As[2][128][20];
    __shared__ float Bs[2][128][20];
    __shared__ float redm[8];
    __shared__ float s_rgm[8][2];
    __shared__ int s_flag;
    int b = blockIdx.y;
    int rr_ = blockIdx.x, dia = 0;
    while (rr_ >= 16 - dia) { rr_ -= 16 - dia; dia++; }
    int ti = rr_, tj = rr_ + dia;
    const float* Cb = g_c + (size_t)b*Ln*Dn;
    int i0 = ti*128, j0 = tj*128;
    int tid = threadIdx.x;
    int warp = tid >> 5, lane = tid & 31;
    int wm = (warp >> 2) * 64;
    int wn = (warp & 3) * 32;
    int g = lane >> 2, th = lane & 3;

    int lrow = tid >> 1, lk = (tid & 1) * 8;
    const float* Ag = Cb + (size_t)(i0 + lrow)*Dn + lk;
    const float* Bg = Cb + (size_t)(j0 + lrow)*Dn + lk;

    float acc[4][4][4];
    #pragma unroll
    for (int i = 0; i < 4; i++)
        #pragma unroll
        for (int j = 0; j < 4; j++)
            #pragma unroll
            for (int q = 0; q < 4; q++) acc[i][j][q] = 0.f;

    float4 pa0 = *(const float4*)(Ag);
    float4 pa1 = *(const float4*)(Ag + 4);
    float4 pb0 = *(const float4*)(Bg);
    float4 pb1 = *(const float4*)(Bg + 4);
    #pragma unroll
    for (int q = 0; q < 4; q++) {
        As[0][lrow][lk+q]   = totf(((float*)&pa0)[q]);
        As[0][lrow][lk+4+q] = totf(((float*)&pa1)[q]);
        Bs[0][lrow][lk+q]   = totf(((float*)&pb0)[q]);
        Bs[0][lrow][lk+4+q] = totf(((float*)&pb1)[q]);
    }
    __syncthreads();
    int cur = 0;
    for (int kt = 0; kt < 32; kt++) {
        if (kt < 31) {
            int ko = (kt+1)*16;
            pa0 = *(const float4*)(Ag + ko);
            pa1 = *(const float4*)(Ag + ko + 4);
            pb0 = *(const float4*)(Bg + ko);
            pb1 = *(const float4*)(Bg + ko + 4);
        }
        #pragma unroll
        for (int k8 = 0; k8 < 16; k8 += 8) {
            unsigned af[4][4], bf_[4][2];
            #pragma unroll
            for (int fm = 0; fm < 4; fm++) {
                const float* ap = &As[cur][wm + fm*16 + g][k8 + th];
                af[fm][0] = __float_as_uint(ap[0]);
                af[fm][1] = __float_as_uint(ap[8*20]);
                af[fm][2] = __float_as_uint(ap[4]);
                af[fm][3] = __float_as_uint(ap[8*20 + 4]);
            }
            #pragma unroll
            for (int fn = 0; fn < 4; fn++) {
                const float* bp = &Bs[cur][wn + fn*8 + g][k8 + th];
                bf_[fn][0] = __float_as_uint(bp[0]);
                bf_[fn][1] = __float_as_uint(bp[4]);
            }
            #pragma unroll
            for (int fm = 0; fm < 4; fm++)
                #pragma unroll
                for (int fn = 0; fn < 4; fn++)
                    mma_tf32(acc[fm][fn], af[fm], bf_[fn]);
        }
        if (ti != tj && (kt == 3 || kt == 7 || kt == 15)) {
            const float* sqp = (kt == 3) ? g_sq64 : (kt == 7) ? g_sq128 : g_sq256;
            float sqj2[4][2];
            #pragma unroll
            for (int fn = 0; fn < 4; fn++) {
                int j = j0 + wn + fn*8 + th*2;
                sqj2[fn][0] = sqp[b*Ln + j];
                sqj2[fn][1] = sqp[b*Ln + j + 1];
            }
            float mind = 1e30f;
            #pragma unroll
            for (int fm = 0; fm < 4; fm++) {
                #pragma unroll
                for (int rr = 0; rr < 2; rr++) {
                    int i = i0 + wm + fm*16 + g + rr*8;
                    float sqi2 = sqp[b*Ln + i];
                    #pragma unroll
                    for (int fn = 0; fn < 4; fn++) {
                        float d0v = sqi2 + sqj2[fn][0] - 2.0f*acc[fm][fn][rr*2+0];
                        float d1v = sqi2 + sqj2[fn][1] - 2.0f*acc[fm][fn][rr*2+1];
                        mind = fminf(mind, fminf(d0v, d1v));
                    }
                }
            }
            #pragma unroll
            for (int o = 16; o; o >>= 1) mind = fminf(mind, __shfl_xor_sync(0xffffffffu, mind, o));
            if (lane == 0) redm[warp] = mind;
            __syncthreads();
            if (tid == 0) {
                float m = redm[0];
                #pragma unroll
                for (int i = 1; i < 8; i++) m = fminf(m, redm[i]);
                s_flag = (m > DCUT) ? 1 : 0;
            }
            __syncthreads();
            if (s_flag) {
                // zero the 4x4 block flags (both orientations)
                if (tid < 16) {
                    int rl = tid >> 2, cl = tid & 3;
                    g_flagB[(b*64 + 4*ti + rl)*64 + 4*tj + cl] = 0;
                    g_flagB[(b*64 + 4*tj + cl)*64 + 4*ti + rl] = 0;
                }
                return;
            }
        }
        if (kt < 31) {
            int nxt = cur ^ 1;
            #pragma unroll
            for (int q = 0; q < 4; q++) {
                As[nxt][lrow][lk+q]   = totf(((float*)&pa0)[q]);
                As[nxt][lrow][lk+4+q] = totf(((float*)&pa1)[q]);
                Bs[nxt][lrow][lk+q]   = totf(((float*)&pb0)[q]);
                Bs[nxt][lrow][lk+4+q] = totf(((float*)&pb1)[q]);
            }
            __syncthreads();
            cur = nxt;
        }
    }
    float sqj[4][2];
    #pragma unroll
    for (int fn = 0; fn < 4; fn++) {
        int j = j0 + wn + fn*8 + th*2;
        sqj[fn][0] = g_sq[b*Ln + j];
        sqj[fn][1] = g_sq[b*Ln + j + 1];
    }
    float rg0 = 0.f, rg1 = 0.f;
    #pragma unroll
    for (int fm = 0; fm < 4; fm++) {
        #pragma unroll
        for (int rr = 0; rr < 2; rr++) {
            int i = i0 + wm + fm*16 + g + rr*8;
            float sqi = g_sq[b*Ln + i];
            #pragma unroll
            for (int fn = 0; fn < 4; fn++) {
                float d0v = fmaxf(sqi + sqj[fn][0] - 2.0f*acc[fm][fn][rr*2+0], 0.0f);
                float d1v = fmaxf(sqi + sqj[fn][1] - 2.0f*acc[fm][fn][rr*2+1], 0.0f);
                float s0 = __expf(-0.5f * d0v);
                float s1 = __expf(-0.5f * d1v);
                acc[fm][fn][rr*2+0] = s0;
                acc[fm][fn][rr*2+1] = s1;
                float m01 = fmaxf(s0, s1);
                if (fm < 2) rg0 = fmaxf(rg0, m01); else rg1 = fmaxf(rg1, m01);
            }
        }
    }
    #pragma unroll
    for (int o = 16; o; o >>= 1) {
        rg0 = fmaxf(rg0, __shfl_xor_sync(0xffffffffu, rg0, o));
        rg1 = fmaxf(rg1, __shfl_xor_sync(0xffffffffu, rg1, o));
    }
    if (lane == 0) { s_rgm[warp][0] = rg0; s_rgm[warp][1] = rg1; }
    __syncthreads();
    if (tid == 0) {
        float tilem = 0.f;
        #pragma unroll
        for (int w = 0; w < 8; w++)
            tilem = fmaxf(tilem, fmaxf(s_rgm[w][0], s_rgm[w][1]));
        s_flag = (tilem > THRESH) ? 1 : 0;
    }
    // 32x32 block flags: warp w covers rows (w>>2)*64 + half*32, cols (w&3)*32
    if (tid < 16) {
        int rl = tid >> 2, cl = tid & 3;                  // local block coords
        int w = (rl >> 1) * 4 + cl, h = rl & 1;
        int fv = (s_rgm[w][h] > THRESH) ? 1 : 0;
        g_flagB[(b*64 + 4*ti + rl)*64 + 4*tj + cl] = fv;
        if (ti != tj)
            g_flagB[(b*64 + 4*tj + cl)*64 + 4*ti + rl] = fv;
    }
    __syncthreads();
    if (s_flag) {
        float* Sb = g_S + (size_t)b*Ln*Ln;
        #pragma unroll
        for (int fm = 0; fm < 4; fm++) {
            #pragma unroll
            for (int rr = 0; rr < 2; rr++) {
                int i = i0 + wm + fm*16 + g + rr*8;
                #pragma unroll
                for (int fn = 0; fn < 4; fn++) {
                    int j = j0 + wn + fn*8 + th*2;
                    float s0 = acc[fm][fn][rr*2+0];
                    float s1 = acc[fm][fn][rr*2+1];
                    *(float2*)&Sb[(size_t)i*Ln + j] = make_float2(s0, s1);
                    if (ti != tj) {
                        Sb[(size_t)j*Ln + i]     = s0;
                        Sb[(size_t)(j+1)*Ln + i] = s1;
                    }
                }
            }
        }
    }
}

// ---------------- 5) sem (32x512 tiles, 2x4 warp grid) + fused LN + mix -------
#define SEM_BS_F (2*16*520)
#define SEM_AS_F (2*32*20)
#define SEM_SMEM_BYTES ((SEM_BS_F + SEM_AS_F + 256 + 128 + 128) * 4)

__global__ __launch_bounds__(256)
void sem_kernel(const float* __restrict__ wp,
                const float* __restrict__ gt, const float* __restrict__ bt,
                float* __restrict__ out) {
    extern __shared__ float sm[];
    float* BsD = sm;
    float* AsD = sm + SEM_BS_F;
    float* srs = AsD + SEM_AS_F;
    float* rsum = srs + 256;
    float* rsq  = rsum + 128;
    __shared__ int s_list[64];
    __shared__ int s_nact;

    int b  = blockIdx.y;
    int i0 = blockIdx.x * 32;
    const float* Cb = g_c + (size_t)b*Ln*Dn;
    const float* Sb = g_S + (size_t)b*Ln*Ln;
    int tid = threadIdx.x;
    int warp = tid >> 5, lane = tid & 31;
    int wmr = (warp >> 2) * 16;
    int wn  = (warp & 3) * 128;
    int g = lane >> 2, th = lane & 3;

    if (tid == 0) {
        const int* fl = g_flagB + (b*64 + blockIdx.x)*64;   // this 32-row chunk's flags
        int n = 0;
        for (int c = 0; c < 64; c++)
            if (fl[c]) s_list[n++] = c;
        s_nact = n;
    }
    __syncthreads();
    int total = s_nact * 2;

    int lrowA = tid >> 3, lkA = (tid & 7) * 2;
    int kB = tid >> 4, cB = tid & 15;
    const float* AgRow = Sb + (size_t)(i0 + lrowA)*Ln + lkA;
    const float* BgRow = Cb + (size_t)kB*Dn;

    float acc[16][4];
    #pragma unroll
    for (int i = 0; i < 16; i++)
        #pragma unroll
        for (int q = 0; q < 4; q++) acc[i][q] = 0.f;

    float rs = 0.f;
    int k0 = s_list[0] * 32;
    float2 pa = *(const float2*)(AgRow + k0);
    float4 pb[8];
    #pragma unroll
    for (int q = 0; q < 8; q++)
        pb[q] = *(const float4*)(BgRow + (size_t)k0*Dn + (cB + q*16)*4);
    rs += pa.x + pa.y;
    {
        float* ad = AsD + lrowA*20 + lkA;
        ad[0] = totf(pa.x); ad[1] = totf(pa.y);
        #pragma unroll
        for (int q = 0; q < 8; q++) {
            float* bd = BsD + kB*520 + (cB + q*16)*4;
            bd[0] = totf(pb[q].x); bd[1] = totf(pb[q].y);
            bd[2] = totf(pb[q].z); bd[3] = totf(pb[q].w);
        }
    }
    __syncthreads();
    int cur = 0;
    for (int st = 0; st < total; st++) {
        if (st + 1 < total) {
            int kn = s_list[(st+1) >> 1] * 32 + ((st+1) & 1) * 16;
            pa = *(const float2*)(AgRow + kn);
            #pragma unroll
            for (int q = 0; q < 8; q++)
                pb[q] = *(const float4*)(BgRow + (size_t)kn*Dn + (cB + q*16)*4);
        }
        const float* AsC = AsD + cur*(32*20);
        const float* BsC = BsD + cur*(16*520);
        #pragma unroll
        for (int k8 = 0; k8 < 16; k8 += 8) {
            unsigned af[4];
            const float* ap = AsC + (wmr + g)*20 + k8 + th;
            af[0] = __float_as_uint(ap[0]);
            af[1] = __float_as_uint(ap[8*20]);
            af[2] = __float_as_uint(ap[4]);
            af[3] = __float_as_uint(ap[8*20 + 4]);
            #pragma unroll
            for (int fn = 0; fn < 16; fn++) {
                unsigned bf_[2];
                const float* bp = BsC + (k8 + th)*520 + wn + fn*8 + g;
                bf_[0] = __float_as_uint(bp[0]);
                bf_[1] = __float_as_uint(bp[4*520]);
                mma_tf32(acc[fn], af, bf_);
            }
        }
        if (st + 1 < total) {
            int nxt = cur ^ 1;
            rs += pa.x + pa.y;
            float* ad = AsD + nxt*(32*20) + lrowA*20 + lkA;
            ad[0] = totf(pa.x); ad[1] = totf(pa.y);
            #pragma unroll
            for (int q = 0; q < 8; q++) {
                float* bd = BsD + nxt*(16*520) + kB*520 + (cB + q*16)*4;
                bd[0] = totf(pb[q].x); bd[1] = totf(pb[q].y);
                bd[2] = totf(pb[q].z); bd[3] = totf(pb[q].w);
            }
            __syncthreads();
            cur = nxt;
        }
    }
    __syncthreads();
    srs[tid] = rs;
    __syncthreads();

    int r0 = wmr + g, r1 = wmr + g + 8;
    float rsum0 = 0.f, rsum1 = 0.f;
    #pragma unroll
    for (int k = 0; k < 8; k++) { rsum0 += srs[r0*8 + k]; rsum1 += srs[r1*8 + k]; }
    float rinv0 = 1.0f / rsum0, rinv1 = 1.0f / rsum1;

    float sum0 = 0.f, sq0 = 0.f, sum1 = 0.f, sq1 = 0.f;
    int gi0 = i0 + r0, gi1 = i0 + r1;
    #pragma unroll
    for (int fn = 0; fn < 16; fn++) {
        int j = wn + fn*8 + th*2;
        float2 cv0 = *(const float2*)&Cb[(size_t)gi0*Dn + j];
        float2 pv0 = *(const float2*)&g_pe[gi0*Dn + j];
        float v00 = cv0.x + pv0.x + acc[fn][0]*rinv0;
        float v01 = cv0.y + pv0.y + acc[fn][1]*rinv0;
        acc[fn][0] = v00; acc[fn][1] = v01;
        sum0 += v00 + v01; sq0 += v00*v00 + v01*v01;
        float2 cv1 = *(const float2*)&Cb[(size_t)gi1*Dn + j];
        float2 pv1 = *(const float2*)&g_pe[gi1*Dn + j];
        float v10 = cv1.x + pv1.x + acc[fn][2]*rinv1;
        float v11 = cv1.y + pv1.y + acc[fn][3]*rinv1;
        acc[fn][2] = v10; acc[fn][3] = v11;
        sum1 += v10 + v11; sq1 += v10*v10 + v11*v11;
    }
    #pragma unroll
    for (int o = 1; o <= 2; o <<= 1) {
        sum0 += __shfl_xor_sync(0xffffffffu, sum0, o);
        sq0  += __shfl_xor_sync(0xffffffffu, sq0, o);
        sum1 += __shfl_xor_sync(0xffffffffu, sum1, o);
        sq1  += __shfl_xor_sync(0xffffffffu, sq1, o);
    }
    if (th == 0) {
        rsum[r0*4 + (warp & 3)] = sum0;  rsq[r0*4 + (warp & 3)] = sq0;
        rsum[r1*4 + (warp & 3)] = sum1;  rsq[r1*4 + (warp & 3)] = sq1;
    }
    __syncthreads();
    float ts0 = rsum[r0*4] + rsum[r0*4+1] + rsum[r0*4+2] + rsum[r0*4+3];
    float tq0 = rsq[r0*4]  + rsq[r0*4+1]  + rsq[r0*4+2]  + rsq[r0*4+3];
    float ts1 = rsum[r1*4] + rsum[r1*4+1] + rsum[r1*4+2] + rsum[r1*4+3];
    float tq1 = rsq[r1*4]  + rsq[r1*4+1]  + rsq[r1*4+2]  + rsq[r1*4+3];
    float mu0 = ts0 * (1.0f/Dn);
    float var0 = tq0 * (1.0f/Dn) - mu0*mu0;
    float inv0 = rsqrtf(var0 + EPSf);
    float mu1 = ts1 * (1.0f/Dn);
    float var1 = tq1 * (1.0f/Dn) - mu1*mu1;
    float inv1 = rsqrtf(var1 + EPSf);

    float w0 = wp[0], w1 = wp[1], w2 = wp[2], w3 = wp[3];
    float mx = fmaxf(fmaxf(w0, w1), fmaxf(w2, w3));
    float e0 = expf(w0-mx), e1 = expf(w1-mx), e2 = expf(w2-mx), e3 = expf(w3-mx);
    float esum = 1.0f / (e0+e1+e2+e3);
    w0 = e0*esum; w1 = e1*esum; w2 = e2*esum; w3 = e3*esum;

    float* ob = out + ((size_t)b*Ln)*Dn;
    #pragma unroll
    for (int fn = 0; fn < 16; fn++) {
        int j = wn + fn*8 + th*2;
        float2 gv = *(const float2*)&gt[j];
        float2 bv = *(const float2*)&bt[j];
        {
            float2 cv = *(const float2*)&Cb[(size_t)gi0*Dn + j];
            float2 pf = *(const float2*)&g_pef[gi0*Dn + j];
            float2 pl = *(const float2*)&g_pel[gi0*Dn + j];
            float t0v = (acc[fn][0]-mu0)*inv0*gv.x + bv.x;
            float t1v = (acc[fn][1]-mu0)*inv0*gv.y + bv.y;
            float2 ov;
            ov.x = w0*cv.x + w1*pf.x + w2*pl.x + w3*t0v;
            ov.y = w0*cv.y + w1*pf.y + w2*pl.y + w3*t1v;
            *(float2*)&ob[(size_t)gi0*Dn + j] = ov;
        }
        {
            float2 cv = *(const float2*)&Cb[(size_t)gi1*Dn + j];
            float2 pf = *(const float2*)&g_pef[gi1*Dn + j];
            float2 pl = *(const float2*)&g_pel[gi1*Dn + j];
            float t0v = (acc[fn][2]-mu1)*inv1*gv.x + bv.x;
            float t1v = (acc[fn][3]-mu1)*inv1*gv.y + bv.y;
            float2 ov;
            ov.x = w0*cv.x + w1*pf.x + w2*pl.x + w3*t0v;
            ov.y = w0*cv.y + w1*pf.y + w2*pl.y + w3*t1v;
            *(float2*)&ob[(size_t)gi1*Dn + j] = ov;
        }
    }
}

// ---------------- launch ------------------------------------------------------
extern "C" void kernel_launch(void* const* d_in, const int* in_sizes, int n_in,
                              void* d_out, int out_size) {
    const float* x          = (const float*)d_in[0];
    const float* conv_w     = (const float*)d_in[1];
    const float* conv_b     = (const float*)d_in[2];
    const float* pe_learned = (const float*)d_in[3];
    const float* wp         = (const float*)d_in[4];
    const float* gamma_c    = (const float*)d_in[5];
    const float* beta_c     = (const float*)d_in[6];
    const float* gamma_f    = (const float*)d_in[7];
    const float* beta_f     = (const float*)d_in[8];
    const float* gamma_l    = (const float*)d_in[9];
    const float* beta_l     = (const float*)d_in[10];
    const float* gamma_t    = (const float*)d_in[11];
    const float* beta_t     = (const float*)d_in[12];

    cudaFuncSetAttribute(sem_kernel, cudaFuncAttributeMaxDynamicSharedMemorySize, SEM_SMEM_BYTES);

    features_kernel<<<dim3(Ln/128, Bn), 256>>>(x, conv_w);
    conv_ln_kernel<<<dim3(Ln/TT, Bn), 256>>>(conv_b, gamma_c, beta_c);
    pe_kernel<<<Ln, 256>>>(pe_learned, gamma_f, beta_f, gamma_l, beta_l);
    gram_kernel<<<dim3(136, Bn), 256>>>();
    sem_kernel<<<dim3(Ln/32, Bn), 256, SEM_SMEM_BYTES>>>(wp, gamma_t, beta_t, (float*)d_out);
}